// round 10
// baseline (speedup 1.0000x reference)
#include <cuda_runtime.h>
#include <cuda_bf16.h>
#include <math.h>

#define NN 50000
#define NE 800000
#define HD 128
#define NG 64
#define POOL_SPLIT 16
#define FULLMASK 0xffffffffu

// ---------------- scratch (device globals; no runtime allocation) ----------------
__device__ int    g_rowptr[NN + 1];
__device__ int    g_fillptr[NN];
__device__ int2   g_csr[NE];            // .x = src index, .y = weight bits

__device__ float4 g_support[NN * 32];   // [NN, 128] viewed as [NN, 32] float4
__device__ float4 g_G1[NN * 32];
__device__ float4 g_G2[NN * 32];
__device__ float4 g_G3[NN * 32];

__device__ float g_ssup[NN];
__device__ float g_score[NN];

__device__ int   g_gstart[NG + 1];

__device__ float g_psum[NG * 3 * POOL_SPLIT * HD];
__device__ float g_pmax[NG * 3 * POOL_SPLIT * HD];
__device__ float g_pooled[NG * 768];   // [avg(384) | max(384)] per graph

__device__ __forceinline__ int clampi(int v, int lo, int hi) {
    return v < lo ? lo : (v > hi ? hi : v);
}

// ---- packed f32x2 helpers ----
__device__ __forceinline__ unsigned long long pack2(float x, float y) {
    unsigned long long r;
    asm("mov.b64 %0, {%1, %2};" : "=l"(r) : "f"(x), "f"(y));
    return r;
}
__device__ __forceinline__ void ffma2(unsigned long long& d,
                                      unsigned long long a, unsigned long long b) {
    asm("fma.rn.f32x2 %0, %1, %2, %0;" : "+l"(d) : "l"(a), "l"(b));
}
__device__ __forceinline__ float2 unpack2(unsigned long long v) {
    float2 r;
    asm("mov.b64 {%0, %1}, %2;" : "=f"(r.x), "=f"(r.y) : "l"(v));
    return r;
}

// ---------------- CSR build (edge_index is int32: [2, NE] row-major) -------------
__global__ void k_zero() {
    int i = blockIdx.x * blockDim.x + threadIdx.x;
    if (i < NN) g_fillptr[i] = 0;
}

__global__ void k_hist(const int* __restrict__ ei) {
    int i = blockIdx.x * blockDim.x + threadIdx.x;
    if (i < NE) {
        int d = clampi(ei[NE + i], 0, NN - 1);
        atomicAdd(&g_fillptr[d], 1);
    }
}

// Single-block scan: 1024 threads, each serially owns CHUNK elements.
__global__ void k_scan() {
    __shared__ int wsum[32];
    const int CHUNK = (NN + 1023) / 1024;      // 49
    int tid  = threadIdx.x;
    int lane = tid & 31, wid = tid >> 5;
    int base = tid * CHUNK;

    int sum = 0;
    for (int i = 0; i < CHUNK; i++) {
        int idx = base + i;
        if (idx < NN) sum += g_fillptr[idx];
    }
    int v = sum;
#pragma unroll
    for (int o = 1; o < 32; o <<= 1) {
        int t = __shfl_up_sync(FULLMASK, v, o);
        if (lane >= o) v += t;
    }
    if (lane == 31) wsum[wid] = v;
    __syncthreads();
    if (wid == 0) {
        int s = wsum[lane];
#pragma unroll
        for (int o = 1; o < 32; o <<= 1) {
            int t = __shfl_up_sync(FULLMASK, s, o);
            if (lane >= o) s += t;
        }
        wsum[lane] = s;
    }
    __syncthreads();

    int run = v - sum + (wid > 0 ? wsum[wid - 1] : 0);   // exclusive prefix
    for (int i = 0; i < CHUNK; i++) {
        int idx = base + i;
        if (idx < NN) {
            int d = g_fillptr[idx];
            g_rowptr[idx]  = run;
            g_fillptr[idx] = run;
            run += d;
        }
    }
    if (tid == 1023) g_rowptr[NN] = run;
}

__global__ void k_fill(const int* __restrict__ ei,
                       const float* __restrict__ ew) {
    int i = blockIdx.x * blockDim.x + threadIdx.x;
    if (i < NE) {
        int s = clampi(ei[i], 0, NN - 1);
        int d = clampi(ei[NE + i], 0, NN - 1);
        int pos = atomicAdd(&g_fillptr[d], 1);
        if (pos < NE) g_csr[pos] = make_int2(s, __float_as_int(ew[i]));
    }
}

// ---------------- dense GEMM: g_support = X @ W  ---------------------------------
// 512 threads, 128 nodes/block (64KB smem). Thread owns 8 nodes x 4 output dims.
__global__ void __launch_bounds__(512)
k_gemm(const float* __restrict__ Xext, const float* __restrict__ W, int sel) {
    __shared__ float xs[128 * HD];          // 64 KB
    const float* X = (sel == 0) ? Xext
                   : (sel == 1) ? (const float*)g_G1
                                : (const float*)g_G2;
    int n0 = blockIdx.x * 128;
    int t = threadIdx.x;

    int nvalid = NN - n0; if (nvalid > 128) nvalid = 128;
    for (int i = t; i < 128 * HD; i += 512) {
        int nl = i >> 7;
        xs[i] = (nl < nvalid) ? X[n0 * HD + i] : 0.0f;
    }
    __syncthreads();

    int rp = t >> 5;          // 0..15 -> node group of 8
    int j4 = t & 31;          // float4 column group
    const ulonglong2* W2 = (const ulonglong2*)W;
    const float* xr = &xs[(8 * rp) * HD];   // 8 consecutive node rows

    unsigned long long a01[8] = {0,0,0,0,0,0,0,0};
    unsigned long long a23[8] = {0,0,0,0,0,0,0,0};

#pragma unroll 4
    for (int k = 0; k < HD; k++) {
        ulonglong2 w = __ldg(&W2[k * 32 + j4]);
#pragma unroll
        for (int m = 0; m < 8; m++) {
            float x = xr[m * HD + k];
            unsigned long long p = pack2(x, x);
            ffma2(a01[m], p, w.x);
            ffma2(a23[m], p, w.y);
        }
    }

    int nb = n0 + 8 * rp;
#pragma unroll
    for (int m = 0; m < 8; m++) {
        if (nb + m < NN) {
            float2 q01 = unpack2(a01[m]), q23 = unpack2(a23[m]);
            g_support[(nb + m) * 32 + j4] = make_float4(q01.x, q01.y, q23.x, q23.y);
        }
    }
}

// ---------------- SpMM gather + fused attention partial dot ---------------------
// out = relu(b + sum_e w_e * support[src_e]);  ssup[n] (+)= dot(out_row, wa_chunk)
// One warp per node. CSR entries fetched cooperatively (1 coalesced LDG per 32
// edges), then broadcast via shfl so the gather is the only latency in the chain.
__global__ void k_spmm(const float* __restrict__ bias,
                       const float* __restrict__ wa_part, int sel) {
    int gt = blockIdx.x * blockDim.x + threadIdx.x;
    int n = gt >> 5;
    int lane = gt & 31;
    if (n >= NN) return;

    float4* out = (sel == 1) ? g_G1 : (sel == 2) ? g_G2 : g_G3;
    int beg = g_rowptr[n];
    int deg = g_rowptr[n + 1] - beg;

    float4 acc0 = make_float4(0.f, 0.f, 0.f, 0.f);
    float4 acc1 = make_float4(0.f, 0.f, 0.f, 0.f);
    float4 acc2 = make_float4(0.f, 0.f, 0.f, 0.f);
    float4 acc3 = make_float4(0.f, 0.f, 0.f, 0.f);

    for (int base = 0; base < deg; base += 32) {
        int m = deg - base; if (m > 32) m = 32;
        int2 c = (lane < m) ? g_csr[beg + base + lane] : make_int2(0, 0);

        int j = 0;
        for (; j + 4 <= m; j += 4) {
            int s0 = __shfl_sync(FULLMASK, c.x, j);
            int s1 = __shfl_sync(FULLMASK, c.x, j + 1);
            int s2 = __shfl_sync(FULLMASK, c.x, j + 2);
            int s3 = __shfl_sync(FULLMASK, c.x, j + 3);
            float w0 = __int_as_float(__shfl_sync(FULLMASK, c.y, j));
            float w1 = __int_as_float(__shfl_sync(FULLMASK, c.y, j + 1));
            float w2 = __int_as_float(__shfl_sync(FULLMASK, c.y, j + 2));
            float w3 = __int_as_float(__shfl_sync(FULLMASK, c.y, j + 3));
            float4 v0 = __ldg(&g_support[s0 * 32 + lane]);
            float4 v1 = __ldg(&g_support[s1 * 32 + lane]);
            float4 v2 = __ldg(&g_support[s2 * 32 + lane]);
            float4 v3 = __ldg(&g_support[s3 * 32 + lane]);
            acc0.x += w0 * v0.x; acc0.y += w0 * v0.y; acc0.z += w0 * v0.z; acc0.w += w0 * v0.w;
            acc1.x += w1 * v1.x; acc1.y += w1 * v1.y; acc1.z += w1 * v1.z; acc1.w += w1 * v1.w;
            acc2.x += w2 * v2.x; acc2.y += w2 * v2.y; acc2.z += w2 * v2.z; acc2.w += w2 * v2.w;
            acc3.x += w3 * v3.x; acc3.y += w3 * v3.y; acc3.z += w3 * v3.z; acc3.w += w3 * v3.w;
        }
        for (; j < m; j++) {
            int s0 = __shfl_sync(FULLMASK, c.x, j);
            float w0 = __int_as_float(__shfl_sync(FULLMASK, c.y, j));
            float4 v0 = __ldg(&g_support[s0 * 32 + lane]);
            acc0.x += w0 * v0.x; acc0.y += w0 * v0.y; acc0.z += w0 * v0.z; acc0.w += w0 * v0.w;
        }
    }

    float4 b = ((const float4*)bias)[lane];
    float4 r;
    r.x = fmaxf(acc0.x + acc1.x + acc2.x + acc3.x + b.x, 0.f);
    r.y = fmaxf(acc0.y + acc1.y + acc2.y + acc3.y + b.y, 0.f);
    r.z = fmaxf(acc0.z + acc1.z + acc2.z + acc3.z + b.z, 0.f);
    r.w = fmaxf(acc0.w + acc1.w + acc2.w + acc3.w + b.w, 0.f);
    out[n * 32 + lane] = r;

    // fused partial of ssup[n] = h[n,:] . wa  (this layer's 128-dim chunk)
    float4 wv = ((const float4*)wa_part)[lane];
    float dot = r.x * wv.x + r.y * wv.y + r.z * wv.z + r.w * wv.w;
#pragma unroll
    for (int o = 16; o > 0; o >>= 1) dot += __shfl_down_sync(FULLMASK, dot, o);
    if (lane == 0) {
        if (sel == 1) g_ssup[n] = dot;
        else          g_ssup[n] += dot;
    }
}

// ---------------- score: gather ssup over edges, tanh ---------------------------
__global__ void k_score(const float* __restrict__ ba) {
    int n = blockIdx.x * blockDim.x + threadIdx.x;
    if (n >= NN) return;
    int beg = g_rowptr[n], end = g_rowptr[n + 1];
    float acc = 0.f;
    for (int e = beg; e < end; e++) {
        int2 c = g_csr[e];
        acc += __int_as_float(c.y) * __ldg(&g_ssup[c.x]);
    }
    g_score[n] = tanhf(acc + ba[0]);
}

// ---------------- per-graph ranges: binary search on sorted indicator ------------
__global__ void k_gbounds(const int* __restrict__ gi) {
    int g = threadIdx.x;
    if (g > NG) return;
    int lo = 0, hi = NN;
    while (lo < hi) {
        int m = (lo + hi) >> 1;
        if (gi[m] < g) lo = m + 1; else hi = m;
    }
    g_gstart[g] = lo;
}

// ---------------- pooling: avg + max of h*score per graph ----------------
__global__ void k_pool() {
    int bx = blockIdx.x;                 // (g, c, s)
    int g = bx / (3 * POOL_SPLIT);
    int c = (bx / POOL_SPLIT) % 3;
    int s = bx % POOL_SPLIT;
    int t = threadIdx.x;                 // dim within chunk

    int gs = g_gstart[g], ge = g_gstart[g + 1];
    const float* H = (c == 0) ? (const float*)g_G1
                   : (c == 1) ? (const float*)g_G2
                              : (const float*)g_G3;

    float sum = 0.f, mx = -INFINITY;
    for (int n = gs + s; n < ge; n += POOL_SPLIT) {
        float v = H[n * HD + t] * g_score[n];
        sum += v;
        mx = fmaxf(mx, v);
    }
    int idx = ((g * 3 + c) * POOL_SPLIT + s) * HD + t;
    g_psum[idx] = sum;
    g_pmax[idx] = mx;
}

__global__ void k_pool_reduce() {
    int bx = blockIdx.x;                 // (g, c)
    int g = bx / 3, c = bx % 3;
    int t = threadIdx.x;

    float sum = 0.f, mx = -INFINITY;
#pragma unroll
    for (int s = 0; s < POOL_SPLIT; s++) {
        int idx = ((g * 3 + c) * POOL_SPLIT + s) * HD + t;
        sum += g_psum[idx];
        mx = fmaxf(mx, g_pmax[idx]);
    }
    int cnt = g_gstart[g + 1] - g_gstart[g];
    float denom = (float)(cnt > 1 ? cnt : 1);
    int j = c * HD + t;
    g_pooled[g * 768 + j]       = sum / denom;
    g_pooled[g * 768 + 384 + j] = mx;
}

// ---------------- final: out[g] = relu(pooled[g] @ Wf + bf) ----------------
__global__ void k_final(const float* __restrict__ Wf,
                        const float* __restrict__ bf,
                        float* __restrict__ out) {
    int g = blockIdx.x;
    int t = threadIdx.x;
    const float* p = &g_pooled[g * 768];
    float acc = bf[t];
#pragma unroll 8
    for (int k = 0; k < 768; k++)
        acc += p[k] * __ldg(&Wf[k * HD + t]);
    out[g * HD + t] = fmaxf(acc, 0.f);
}

// ---------------- launch (pure kernel launches; graph-capturable) ----------------
extern "C" void kernel_launch(void* const* d_in, const int* in_sizes, int n_in,
                              void* d_out, int out_size) {
    const int*   edge_index = (const int*)d_in[0];     // int32 [2, NE]
    const float* edge_w     = (const float*)d_in[1];
    const float* x_in       = (const float*)d_in[2];
    const int*   gind       = (const int*)d_in[3];     // int32 [NN]
    const float* W1 = (const float*)d_in[4];
    const float* b1 = (const float*)d_in[5];
    const float* W2 = (const float*)d_in[6];
    const float* b2 = (const float*)d_in[7];
    const float* W3 = (const float*)d_in[8];
    const float* b3 = (const float*)d_in[9];
    const float* wa = (const float*)d_in[10];
    const float* ba = (const float*)d_in[11];
    const float* Wf = (const float*)d_in[12];
    const float* bf = (const float*)d_in[13];
    float* out = (float*)d_out;

    const int gemm_grid = (NN + 127) / 128;
    const int spmm_grid = (NN * 32 + 255) / 256;   // exactly NN warps

    // layer-1 GEMM needs no CSR -> launch 0 (moves heavy kernels into ncu window)
    k_gemm<<<gemm_grid, 512>>>(x_in, W1, 0);

    // CSR build (launches 1-4)
    k_zero<<<(NN + 255) / 256, 256>>>();
    k_hist<<<(NE + 255) / 256, 256>>>(edge_index);
    k_scan<<<1, 1024>>>();
    k_fill<<<(NE + 255) / 256, 256>>>(edge_index, edge_w);

    // launch 5 = spmm1
    k_spmm<<<spmm_grid, 256>>>(b1, wa + 0 * HD, 1);
    k_gemm<<<gemm_grid, 512>>>(x_in, W2, 1);
    k_spmm<<<spmm_grid, 256>>>(b2, wa + 1 * HD, 2);
    k_gemm<<<gemm_grid, 512>>>(x_in, W3, 2);
    k_spmm<<<spmm_grid, 256>>>(b3, wa + 2 * HD, 3);

    // attention score (ssup fused into spmm above)
    k_score<<<(NN + 255) / 256, 256>>>(ba);

    // per-graph ranges + pooling
    k_gbounds<<<1, NG + 1>>>(gind);
    k_pool<<<NG * 3 * POOL_SPLIT, HD>>>();
    k_pool_reduce<<<NG * 3, HD>>>();

    // output head
    k_final<<<NG, HD>>>(Wf, bf, out);
}